// round 1
// baseline (speedup 1.0000x reference)
#include <cuda_runtime.h>
#include <cstdint>
#include <cstddef>

// Problem constants
#define B_  4096
#define T_  32
#define H_  16
#define HS_ 32
#define E_  512

// Scratch: qkv laid out [B][H][{q,k,v}][T][HS]; Y laid out [B][HS][H*T]
__device__ float g_qkv[(size_t)B_ * H_ * 3 * T_ * HS_];   // 201,326,592 floats
__device__ float g_y[(size_t)B_ * HS_ * (H_ * T_)];       //  67,108,864 floats

__device__ __forceinline__ uint32_t f2tf(float f) {
    uint32_t r;
    asm("cvt.rna.tf32.f32 %0, %1;" : "=r"(r) : "f"(f));
    return r;
}

#define MMA_TF32(d, a, b)                                                   \
    asm volatile(                                                           \
        "mma.sync.aligned.m16n8k8.row.col.f32.tf32.tf32.f32 "               \
        "{%0,%1,%2,%3}, {%4,%5,%6,%7}, {%8,%9}, {%0,%1,%2,%3};\n"           \
        : "+f"((d)[0]), "+f"((d)[1]), "+f"((d)[2]), "+f"((d)[3])            \
        : "r"((a)[0]), "r"((a)[1]), "r"((a)[2]), "r"((a)[3]),               \
          "r"((b)[0]), "r"((b)[1]))

__device__ __forceinline__ int qkv_index(int m, int n) {
    // m = b*32 + t ; n = sel*512 + h*32 + d
    const int sel = n >> 9;
    const int r   = n & 511;
    const int h   = r >> 5;
    const int d   = r & 31;
    const int b   = m >> 5;
    const int t   = m & 31;
    return ((b * 16 + h) * 3 + sel) * 1024 + t * 32 + d;
}

// ---------------------------------------------------------------------------
// Tiled TF32 GEMM: C[M,N] = A[M,512] * W[N,512]^T
// MODE 0: A = x, W = {Wq,Wk,Wv} concatenated along N; epilogue scatters to g_qkv
// MODE 1: A = g_y, W = Wp; epilogue adds bias and writes d_out
// BM=128, BN=128, BK=32, 512 threads, warp tile 32x32 (4x4 warp grid)
// ---------------------------------------------------------------------------
template <int MODE>
__global__ __launch_bounds__(512, 1)
void gemm_tf32_kernel(const float* __restrict__ Ain,
                      const float* __restrict__ B0,
                      const float* __restrict__ B1,
                      const float* __restrict__ B2,
                      const float* __restrict__ bias,
                      float* __restrict__ Cout)
{
    __shared__ uint32_t sA[128][36];   // stride 36 -> conflict-free frag lds
    __shared__ uint32_t sB[128][36];

    const int tid  = threadIdx.x;
    const int lane = tid & 31;
    const int warp = tid >> 5;
    const int wm = warp & 3;           // warp row (M)
    const int wn = warp >> 2;          // warp col (N)
    const int g  = lane >> 2;          // groupID
    const int t4 = lane & 3;           // threadID in group

    const int n0 = blockIdx.x * 128;
    const int m0 = blockIdx.y * 128;

    const float* Asrc = (MODE == 0) ? Ain : (const float*)g_y;

    const int rL = tid >> 3;           // 0..63 (tile row for loading)
    const int cL = (tid & 7) * 4;      // 0..28 (tile col, float4 granularity)

    const float4* ag0 = reinterpret_cast<const float4*>(Asrc + (size_t)(m0 + rL) * 512) + (tid & 7);
    const float4* ag1 = reinterpret_cast<const float4*>(Asrc + (size_t)(m0 + 64 + rL) * 512) + (tid & 7);

    const float* Bsel;
    int nbase;
    if (MODE == 0) {
        const int sel = n0 >> 9;                 // a 128-wide tile never straddles q/k/v
        Bsel  = (sel == 0) ? B0 : ((sel == 1) ? B1 : B2);
        nbase = n0 & 511;
    } else {
        Bsel  = B0;
        nbase = n0;
    }
    const float4* bg0 = reinterpret_cast<const float4*>(Bsel + (size_t)(nbase + rL) * 512) + (tid & 7);
    const float4* bg1 = reinterpret_cast<const float4*>(Bsel + (size_t)(nbase + 64 + rL) * 512) + (tid & 7);

    float acc[2][4][4];
    #pragma unroll
    for (int i = 0; i < 2; ++i)
        #pragma unroll
        for (int j = 0; j < 4; ++j)
            #pragma unroll
            for (int q = 0; q < 4; ++q) acc[i][j][q] = 0.f;

    float4 ra0 = ag0[0], ra1 = ag1[0], rb0 = bg0[0], rb1 = bg1[0];

    for (int it = 0; it < 16; ++it) {
        // stage registers -> smem (convert to tf32 once here)
        {
            uint4 u;
            u.x = f2tf(ra0.x); u.y = f2tf(ra0.y); u.z = f2tf(ra0.z); u.w = f2tf(ra0.w);
            *reinterpret_cast<uint4*>(&sA[rL][cL]) = u;
            u.x = f2tf(ra1.x); u.y = f2tf(ra1.y); u.z = f2tf(ra1.z); u.w = f2tf(ra1.w);
            *reinterpret_cast<uint4*>(&sA[64 + rL][cL]) = u;
            u.x = f2tf(rb0.x); u.y = f2tf(rb0.y); u.z = f2tf(rb0.z); u.w = f2tf(rb0.w);
            *reinterpret_cast<uint4*>(&sB[rL][cL]) = u;
            u.x = f2tf(rb1.x); u.y = f2tf(rb1.y); u.z = f2tf(rb1.z); u.w = f2tf(rb1.w);
            *reinterpret_cast<uint4*>(&sB[64 + rL][cL]) = u;
        }
        __syncthreads();

        if (it < 15) {                 // prefetch next K-slab while we do math
            const int o = (it + 1) * 8;
            ra0 = ag0[o]; ra1 = ag1[o]; rb0 = bg0[o]; rb1 = bg1[o];
        }

        #pragma unroll
        for (int kk = 0; kk < 4; ++kk) {
            const int kb = kk * 8;
            uint32_t af[2][4], bf[4][2];
            #pragma unroll
            for (int im = 0; im < 2; ++im) {
                const int rb_ = wm * 32 + im * 16;
                af[im][0] = sA[rb_ + g][kb + t4];
                af[im][1] = sA[rb_ + g + 8][kb + t4];
                af[im][2] = sA[rb_ + g][kb + t4 + 4];
                af[im][3] = sA[rb_ + g + 8][kb + t4 + 4];
            }
            #pragma unroll
            for (int in_ = 0; in_ < 4; ++in_) {
                const int cb = wn * 32 + in_ * 8;
                bf[in_][0] = sB[cb + g][kb + t4];
                bf[in_][1] = sB[cb + g][kb + t4 + 4];
            }
            #pragma unroll
            for (int im = 0; im < 2; ++im)
                #pragma unroll
                for (int in_ = 0; in_ < 4; ++in_)
                    MMA_TF32(acc[im][in_], af[im], bf[in_]);
        }
        __syncthreads();
    }

    // epilogue
    #pragma unroll
    for (int im = 0; im < 2; ++im) {
        #pragma unroll
        for (int in_ = 0; in_ < 4; ++in_) {
            const int mr = m0 + wm * 32 + im * 16 + g;
            const int nc = n0 + wn * 32 + in_ * 8 + 2 * t4;
            if (MODE == 0) {
                g_qkv[qkv_index(mr,     nc    )] = acc[im][in_][0];
                g_qkv[qkv_index(mr,     nc + 1)] = acc[im][in_][1];
                g_qkv[qkv_index(mr + 8, nc    )] = acc[im][in_][2];
                g_qkv[qkv_index(mr + 8, nc + 1)] = acc[im][in_][3];
            } else {
                Cout[(size_t)mr * 512 + nc]           = acc[im][in_][0] + bias[nc];
                Cout[(size_t)mr * 512 + nc + 1]       = acc[im][in_][1] + bias[nc + 1];
                Cout[(size_t)(mr + 8) * 512 + nc]     = acc[im][in_][2] + bias[nc];
                Cout[(size_t)(mr + 8) * 512 + nc + 1] = acc[im][in_][3] + bias[nc + 1];
            }
        }
    }
}

// ---------------------------------------------------------------------------
// Attention: one warp per (b,h). 32x32 causal softmax attention via tf32 mma.
// Writes the reference's concat-on-time transpose directly: Y[b][d][h*32+t].
// ---------------------------------------------------------------------------
__global__ __launch_bounds__(64, 1)
void attn_kernel()
{
    __shared__ uint32_t sq[2][32][36];
    __shared__ uint32_t sk[2][32][36];
    __shared__ uint32_t sv[2][32][36];   // v transposed: sv[d][s]
    __shared__ uint32_t sw[2][32][36];   // softmax weights (tf32 bits)
    __shared__ float    so[2][32][36];   // out transposed: so[d][t]

    const int wid  = threadIdx.x >> 5;
    const int lane = threadIdx.x & 31;
    const int bh   = blockIdx.x * 2 + wid;
    const int b    = bh >> 4;
    const int h    = bh & 15;
    const int g  = lane >> 2;
    const int t4 = lane & 3;

    const float* base = g_qkv + (size_t)bh * 3072;

    for (int i = lane; i < 1024; i += 32) {
        const int r = i >> 5, c = i & 31;
        sq[wid][r][c] = f2tf(base[i]);
        sk[wid][r][c] = f2tf(base[1024 + i]);
        sv[wid][c][r] = f2tf(base[2048 + i]);   // transpose V
    }
    __syncwarp();

    // --- wei = q @ k^T ---
    float accw[2][4][4];
    #pragma unroll
    for (int i = 0; i < 2; ++i)
        #pragma unroll
        for (int j = 0; j < 4; ++j)
            #pragma unroll
            for (int q = 0; q < 4; ++q) accw[i][j][q] = 0.f;

    #pragma unroll
    for (int kk = 0; kk < 4; ++kk) {
        const int kb = kk * 8;
        uint32_t af[2][4], bf[4][2];
        #pragma unroll
        for (int im = 0; im < 2; ++im) {
            const int rb_ = im * 16;
            af[im][0] = sq[wid][rb_ + g][kb + t4];
            af[im][1] = sq[wid][rb_ + g + 8][kb + t4];
            af[im][2] = sq[wid][rb_ + g][kb + t4 + 4];
            af[im][3] = sq[wid][rb_ + g + 8][kb + t4 + 4];
        }
        #pragma unroll
        for (int in_ = 0; in_ < 4; ++in_) {
            const int cb = in_ * 8;
            bf[in_][0] = sk[wid][cb + g][kb + t4];
            bf[in_][1] = sk[wid][cb + g][kb + t4 + 4];
        }
        #pragma unroll
        for (int im = 0; im < 2; ++im)
            #pragma unroll
            for (int in_ = 0; in_ < 4; ++in_)
                MMA_TF32(accw[im][in_], af[im], bf[in_]);
    }

    // --- causal softmax on C fragments (row quad = 4 consecutive lanes) ---
    const float scale = 0.17677669529663687f;   // 32^-0.5
    #pragma unroll
    for (int im = 0; im < 2; ++im) {
        #pragma unroll
        for (int hf = 0; hf < 2; ++hf) {
            const int row = im * 16 + hf * 8 + g;
            float vals[8];
            float mx = -1e30f;
            #pragma unroll
            for (int in_ = 0; in_ < 4; ++in_) {
                #pragma unroll
                for (int cc = 0; cc < 2; ++cc) {
                    const int col = in_ * 8 + 2 * t4 + cc;
                    float s = accw[im][in_][hf * 2 + cc] * scale;
                    if (col > row) s = -1e30f;       // causal mask
                    vals[in_ * 2 + cc] = s;
                    mx = fmaxf(mx, s);
                }
            }
            mx = fmaxf(mx, __shfl_xor_sync(0xffffffffu, mx, 1));
            mx = fmaxf(mx, __shfl_xor_sync(0xffffffffu, mx, 2));
            float sum = 0.f;
            #pragma unroll
            for (int j = 0; j < 8; ++j) { vals[j] = __expf(vals[j] - mx); sum += vals[j]; }
            sum += __shfl_xor_sync(0xffffffffu, sum, 1);
            sum += __shfl_xor_sync(0xffffffffu, sum, 2);
            const float inv = 1.f / sum;
            #pragma unroll
            for (int in_ = 0; in_ < 4; ++in_)
                #pragma unroll
                for (int cc = 0; cc < 2; ++cc)
                    sw[wid][row][in_ * 8 + 2 * t4 + cc] = f2tf(vals[in_ * 2 + cc] * inv);
        }
    }
    __syncwarp();

    // --- out = wei @ v ---
    float acco[2][4][4];
    #pragma unroll
    for (int i = 0; i < 2; ++i)
        #pragma unroll
        for (int j = 0; j < 4; ++j)
            #pragma unroll
            for (int q = 0; q < 4; ++q) acco[i][j][q] = 0.f;

    #pragma unroll
    for (int kk = 0; kk < 4; ++kk) {
        const int kb = kk * 8;
        uint32_t af[2][4], bf[4][2];
        #pragma unroll
        for (int im = 0; im < 2; ++im) {
            const int rb_ = im * 16;
            af[im][0] = sw[wid][rb_ + g][kb + t4];
            af[im][1] = sw[wid][rb_ + g + 8][kb + t4];
            af[im][2] = sw[wid][rb_ + g][kb + t4 + 4];
            af[im][3] = sw[wid][rb_ + g + 8][kb + t4 + 4];
        }
        #pragma unroll
        for (int in_ = 0; in_ < 4; ++in_) {
            const int cb = in_ * 8;
            bf[in_][0] = sv[wid][cb + g][kb + t4];       // B[s][d] = sv[d][s]
            bf[in_][1] = sv[wid][cb + g][kb + t4 + 4];
        }
        #pragma unroll
        for (int im = 0; im < 2; ++im)
            #pragma unroll
            for (int in_ = 0; in_ < 4; ++in_)
                MMA_TF32(acco[im][in_], af[im], bf[in_]);
    }

    // stage transposed into smem, then coalesced write to Y[b][d][h*32+t]
    #pragma unroll
    for (int im = 0; im < 2; ++im) {
        #pragma unroll
        for (int in_ = 0; in_ < 4; ++in_) {
            const int tr = im * 16 + g;
            const int dc = in_ * 8 + 2 * t4;
            so[wid][dc][tr]         = acco[im][in_][0];
            so[wid][dc + 1][tr]     = acco[im][in_][1];
            so[wid][dc][tr + 8]     = acco[im][in_][2];
            so[wid][dc + 1][tr + 8] = acco[im][in_][3];
        }
    }
    __syncwarp();

    float* Y = g_y + (size_t)b * 32 * 512 + h * 32;
    for (int i = lane; i < 1024; i += 32) {
        const int d = i >> 5, tc = i & 31;
        Y[(size_t)d * 512 + tc] = so[wid][d][tc];
    }
}

// ---------------------------------------------------------------------------
extern "C" void kernel_launch(void* const* d_in, const int* in_sizes, int n_in,
                              void* d_out, int out_size)
{
    const float* x  = (const float*)d_in[0];
    const float* Wq = (const float*)d_in[1];
    const float* Wk = (const float*)d_in[2];
    const float* Wv = (const float*)d_in[3];
    const float* Wp = (const float*)d_in[4];
    const float* bp = (const float*)d_in[5];
    float* out = (float*)d_out;

    // 1) QKV projection: C[131072,1536] = x @ [Wq;Wk;Wv]^T -> g_qkv
    gemm_tf32_kernel<0><<<dim3(12, 1024), 512>>>(x, Wq, Wk, Wv, nullptr, nullptr);

    // 2) per-(b,h) causal attention -> g_y (concat-on-time transpose layout)
    attn_kernel<<<32768, 64>>>();

    // 3) output projection: out = Y @ Wp^T + bp
    gemm_tf32_kernel<1><<<dim3(4, 1024), 512>>>(nullptr, Wp, nullptr, nullptr, bp, out);
}

// round 5
// speedup vs baseline: 1.2645x; 1.2645x over previous
#include <cuda_runtime.h>
#include <cstdint>
#include <cstddef>

// Problem constants
#define B_  4096
#define T_  32
#define H_  16
#define HS_ 32
#define E_  512

// Scratch (tf32 bit patterns unless noted)
__device__ uint32_t g_xt[(size_t)B_ * T_ * E_];           // x converted to tf32
__device__ uint32_t g_wt[3 * E_ * E_];                    // [Wq;Wk;Wv] rows 0..1535
__device__ uint32_t g_wpt[E_ * E_];                       // Wp
__device__ uint32_t g_qkv[(size_t)B_ * H_ * 3 * T_ * HS_];// [B][H][{q,k,v}][T][HS] tf32 bits
__device__ uint32_t g_y[(size_t)B_ * HS_ * (H_ * T_)];    // [B][HS][H*T] tf32 bits

__device__ __forceinline__ uint32_t f2tf(float f) {
    uint32_t r;
    asm("cvt.rna.tf32.f32 %0, %1;" : "=r"(r) : "f"(f));
    return r;
}

#define MMA_TF32(d, a, b)                                                   \
    asm volatile(                                                           \
        "mma.sync.aligned.m16n8k8.row.col.f32.tf32.tf32.f32 "               \
        "{%0,%1,%2,%3}, {%4,%5,%6,%7}, {%8,%9}, {%0,%1,%2,%3};\n"           \
        : "+f"((d)[0]), "+f"((d)[1]), "+f"((d)[2]), "+f"((d)[3])            \
        : "r"((a)[0]), "r"((a)[1]), "r"((a)[2]), "r"((a)[3]),               \
          "r"((b)[0]), "r"((b)[1]))

__device__ __forceinline__ size_t qkv_index(int m, int n) {
    // m = b*32 + t ; n = sel*512 + h*32 + d
    const int sel = n >> 9;
    const int r   = n & 511;
    const int h   = r >> 5;
    const int d   = r & 31;
    const int b   = m >> 5;
    const int t   = m & 31;
    return (size_t)((b * 16 + h) * 3 + sel) * 1024 + t * 32 + d;
}

// ---------------------------------------------------------------------------
// fp32 -> tf32 bit conversion, float4 granularity
// ---------------------------------------------------------------------------
__global__ void conv_tf32_kernel(const float4* __restrict__ in,
                                 uint4* __restrict__ out, int n4)
{
    const int i = blockIdx.x * blockDim.x + threadIdx.x;
    if (i < n4) {
        float4 f = in[i];
        uint4 u;
        u.x = f2tf(f.x); u.y = f2tf(f.y); u.z = f2tf(f.z); u.w = f2tf(f.w);
        out[i] = u;
    }
}

// ---------------------------------------------------------------------------
// 4-stage cp.async TF32 GEMM: C[M,N] = A[M,512] * W[N,512]^T
// MODE 0: A = g_xt, W = g_wt (N=1536), epilogue scatters tf32 bits -> g_qkv
// MODE 1: A = g_y,  W = g_wpt (N=512), epilogue += bias, f32 -> d_out
// BM=128, BN=128, BK=32, 512 threads, warp tile 32x32 (4x4 warp grid)
// ---------------------------------------------------------------------------
#define STAGES 4
#define SLOTU  (2 * 128 * 36)   // uints per pipeline stage (A tile + B tile)

template <int MODE>
__global__ __launch_bounds__(512)
void gemm2_kernel(const uint32_t* __restrict__ A,
                  const uint32_t* __restrict__ Bw,
                  const float* __restrict__ bias,
                  float* __restrict__ Cout)
{
    extern __shared__ uint32_t sm[];

    const int tid  = threadIdx.x;
    const int lane = tid & 31;
    const int warp = tid >> 5;
    const int wm = warp & 3;
    const int wn = warp >> 2;
    const int g  = lane >> 2;
    const int t4 = lane & 3;

    const int n0 = blockIdx.x * 128;
    const int m0 = blockIdx.y * 128;

    // per-thread cp.async descriptors: 4 x 16B chunks per stage
    const uint32_t* src[4];
    uint32_t dstoff[4];
    #pragma unroll
    for (int c = 0; c < 4; ++c) {
        const int chunk = tid + c * 512;          // 0..2047
        const int mat = chunk >> 10;              // 0=A, 1=B
        const int idx = chunk & 1023;
        const int row = idx >> 3;
        const int col = (idx & 7) << 2;
        src[c] = (mat == 0 ? A + (size_t)(m0 + row) * 512
                           : Bw + (size_t)(n0 + row) * 512) + col;
        dstoff[c] = (uint32_t)(((mat * 128 + row) * 36 + col) * 4); // byte offset
    }

    uint32_t smbase;
    asm("{ .reg .u64 t; cvta.to.shared.u64 t, %1; cvt.u32.u64 %0, t; }"
        : "=r"(smbase) : "l"(sm));

    auto load_stage = [&](int s, int kt) {
        const uint32_t sb = smbase + (uint32_t)(s * SLOTU) * 4;
        #pragma unroll
        for (int c = 0; c < 4; ++c)
            asm volatile("cp.async.cg.shared.global [%0], [%1], 16;"
                         :: "r"(sb + dstoff[c]), "l"(src[c] + kt * 32));
    };

    #pragma unroll
    for (int s = 0; s < STAGES - 1; ++s) {
        load_stage(s, s);
        asm volatile("cp.async.commit_group;");
    }

    float acc[2][4][4];
    #pragma unroll
    for (int i = 0; i < 2; ++i)
        #pragma unroll
        for (int j = 0; j < 4; ++j)
            #pragma unroll
            for (int q = 0; q < 4; ++q) acc[i][j][q] = 0.f;

    #pragma unroll 4
    for (int it = 0; it < 16; ++it) {
        asm volatile("cp.async.wait_group %0;" :: "n"(STAGES - 2));
        __syncthreads();
        if (it + STAGES - 1 < 16)
            load_stage((it + STAGES - 1) & 3, it + STAGES - 1);
        asm volatile("cp.async.commit_group;");   // empty groups keep counts aligned

        const uint32_t* As = sm + (it & 3) * SLOTU;
        const uint32_t* Bs = As + 128 * 36;

        #pragma unroll
        for (int kk = 0; kk < 4; ++kk) {
            const int kb = kk * 8;
            uint32_t af[2][4], bf[4][2];
            #pragma unroll
            for (int im = 0; im < 2; ++im) {
                const int rb_ = wm * 32 + im * 16;
                af[im][0] = As[(rb_ + g) * 36 + kb + t4];
                af[im][1] = As[(rb_ + g + 8) * 36 + kb + t4];
                af[im][2] = As[(rb_ + g) * 36 + kb + t4 + 4];
                af[im][3] = As[(rb_ + g + 8) * 36 + kb + t4 + 4];
            }
            #pragma unroll
            for (int in_ = 0; in_ < 4; ++in_) {
                const int cb = wn * 32 + in_ * 8;
                bf[in_][0] = Bs[(cb + g) * 36 + kb + t4];
                bf[in_][1] = Bs[(cb + g) * 36 + kb + t4 + 4];
            }
            #pragma unroll
            for (int im = 0; im < 2; ++im)
                #pragma unroll
                for (int in_ = 0; in_ < 4; ++in_)
                    MMA_TF32(acc[im][in_], af[im], bf[in_]);
        }
    }

    // epilogue
    #pragma unroll
    for (int im = 0; im < 2; ++im) {
        #pragma unroll
        for (int in_ = 0; in_ < 4; ++in_) {
            const int mr = m0 + wm * 32 + im * 16 + g;
            const int nc = n0 + wn * 32 + in_ * 8 + 2 * t4;
            if (MODE == 0) {
                uint2 u0 = { f2tf(acc[im][in_][0]), f2tf(acc[im][in_][1]) };
                uint2 u1 = { f2tf(acc[im][in_][2]), f2tf(acc[im][in_][3]) };
                *reinterpret_cast<uint2*>(&g_qkv[qkv_index(mr,     nc)]) = u0;
                *reinterpret_cast<uint2*>(&g_qkv[qkv_index(mr + 8, nc)]) = u1;
            } else {
                float2 f0 = { acc[im][in_][0] + bias[nc], acc[im][in_][1] + bias[nc + 1] };
                float2 f1 = { acc[im][in_][2] + bias[nc], acc[im][in_][3] + bias[nc + 1] };
                *reinterpret_cast<float2*>(&Cout[(size_t)mr * 512 + nc])       = f0;
                *reinterpret_cast<float2*>(&Cout[(size_t)(mr + 8) * 512 + nc]) = f1;
            }
        }
    }
}

// ---------------------------------------------------------------------------
// Attention: one warp per (b,h); q/k/v already tf32 bits in g_qkv.
// Output written as tf32 bits to g_y in concat-on-time transpose layout.
// ---------------------------------------------------------------------------
__global__ __launch_bounds__(64)
void attn_kernel()
{
    __shared__ uint32_t sq[2][32][36];   // q, later reused for transposed out bits
    __shared__ uint32_t sk[2][32][36];
    __shared__ uint32_t sv[2][32][36];   // v transposed: sv[d][s]
    __shared__ uint32_t sw[2][32][36];   // softmax weights (tf32 bits)

    const int wid  = threadIdx.x >> 5;
    const int lane = threadIdx.x & 31;
    const int bh   = blockIdx.x * 2 + wid;
    const int b    = bh >> 4;
    const int h    = bh & 15;
    const int g  = lane >> 2;
    const int t4 = lane & 3;

    const uint32_t* base = g_qkv + (size_t)bh * 3072;

    for (int i = lane; i < 1024; i += 32) {
        const int r = i >> 5, c = i & 31;
        sq[wid][r][c] = base[i];
        sk[wid][r][c] = base[1024 + i];
        sv[wid][c][r] = base[2048 + i];   // transpose V
    }
    __syncwarp();

    // --- wei = q @ k^T ---
    float accw[2][4][4];
    #pragma unroll
    for (int i = 0; i < 2; ++i)
        #pragma unroll
        for (int j = 0; j < 4; ++j)
            #pragma unroll
            for (int q = 0; q < 4; ++q) accw[i][j][q] = 0.f;

    #pragma unroll
    for (int kk = 0; kk < 4; ++kk) {
        const int kb = kk * 8;
        uint32_t af[2][4], bf[4][2];
        #pragma unroll
        for (int im = 0; im < 2; ++im) {
            const int rb_ = im * 16;
            af[im][0] = sq[wid][rb_ + g][kb + t4];
            af[im][1] = sq[wid][rb_ + g + 8][kb + t4];
            af[im][2] = sq[wid][rb_ + g][kb + t4 + 4];
            af[im][3] = sq[wid][rb_ + g + 8][kb + t4 + 4];
        }
        #pragma unroll
        for (int in_ = 0; in_ < 4; ++in_) {
            const int cb = in_ * 8;
            bf[in_][0] = sk[wid][cb + g][kb + t4];
            bf[in_][1] = sk[wid][cb + g][kb + t4 + 4];
        }
        #pragma unroll
        for (int im = 0; im < 2; ++im)
            #pragma unroll
            for (int in_ = 0; in_ < 4; ++in_)
                MMA_TF32(accw[im][in_], af[im], bf[in_]);
    }

    // --- causal softmax on C fragments ---
    const float scale = 0.17677669529663687f;   // 32^-0.5
    #pragma unroll
    for (int im = 0; im < 2; ++im) {
        #pragma unroll
        for (int hf = 0; hf < 2; ++hf) {
            const int row = im * 16 + hf * 8 + g;
            float vals[8];
            float mx = -1e30f;
            #pragma unroll
            for (int in_ = 0; in_ < 4; ++in_) {
                #pragma unroll
                for (int cc = 0; cc < 2; ++cc) {
                    const int col = in_ * 8 + 2 * t4 + cc;
                    float s = accw[im][in_][hf * 2 + cc] * scale;
                    if (col > row) s = -1e30f;
                    vals[in_ * 2 + cc] = s;
                    mx = fmaxf(mx, s);
                }
            }
            mx = fmaxf(mx, __shfl_xor_sync(0xffffffffu, mx, 1));
            mx = fmaxf(mx, __shfl_xor_sync(0xffffffffu, mx, 2));
            float sum = 0.f;
            #pragma unroll
            for (int j = 0; j < 8; ++j) { vals[j] = __expf(vals[j] - mx); sum += vals[j]; }
            sum += __shfl_xor_sync(0xffffffffu, sum, 1);
            sum += __shfl_xor_sync(0xffffffffu, sum, 2);
            const float inv = 1.f / sum;
            #pragma unroll
            for (int in_ = 0; in_ < 4; ++in_)
                #pragma unroll
                for (int cc = 0; cc < 2; ++cc)
                    sw[wid][row][in_ * 8 + 2 * t4 + cc] = f2tf(vals[in_ * 2 + cc] * inv);
        }
    }
    __syncwarp();

    // --- out = wei @ v ---
    float acco[2][4][4];
    #pragma unroll
    for (int i = 0; i < 2; ++i)
        #pragma unroll
        for (int j = 0; j < 4; ++j)
            #pragma unroll
            for (int q = 0; q < 4; ++q) acco[i][j][q] = 0.f;

    #pragma unroll
    for (int kk = 0; kk < 4; ++kk) {
        const int kb = kk * 8;
        uint32_t af[2][4], bf[4][2];
        #pragma unroll
        for (int im = 0; im < 2; ++im) {
            const int rb_ = im * 16;
            af[im][0] = sw[wid][rb_ + g][kb + t4];
            af[im][1] = sw[wid][rb_ + g + 8][kb + t4];
            af[im][2] = sw[wid][rb_ + g][kb + t4 + 4];
            af[im][3] = sw[wid][rb_ + g + 8][kb + t4 + 4];
        }
        #pragma unroll
        for (int in_ = 0; in_ < 4; ++in_) {
            const int cb = in_ * 8;
            bf[in_][0] = sv[wid][cb + g][kb + t4];
            bf[in_][1] = sv[wid][cb + g][kb + t4 + 4];
        }
        #pragma unroll
        for (int im = 0; im < 2; ++im)
            #pragma unroll
            for (int in_ = 0; in_ < 4; ++in_)
                MMA_TF32(acco[im][in_], af[im], bf[in_]);
    }

    // stage transposed tf32 bits into sq (reuse), then coalesced write to g_y
    __syncwarp();
    #pragma unroll
    for (int im = 0; im < 2; ++im) {
        #pragma unroll
        for (int in_ = 0; in_ < 4; ++in_) {
            const int tr = im * 16 + g;
            const int dc = in_ * 8 + 2 * t4;
            sq[wid][dc][tr]         = f2tf(acco[im][in_][0]);
            sq[wid][dc + 1][tr]     = f2tf(acco[im][in_][1]);
            sq[wid][dc][tr + 8]     = f2tf(acco[im][in_][2]);
            sq[wid][dc + 1][tr + 8] = f2tf(acco[im][in_][3]);
        }
    }
    __syncwarp();

    uint32_t* Y = g_y + (size_t)b * 32 * 512 + h * 32;
    for (int i = lane; i < 1024; i += 32) {
        const int d = i >> 5, tc = i & 31;
        Y[(size_t)d * 512 + tc] = sq[wid][d][tc];
    }
}

// ---------------------------------------------------------------------------
extern "C" void kernel_launch(void* const* d_in, const int* in_sizes, int n_in,
                              void* d_out, int out_size)
{
    const float* x  = (const float*)d_in[0];
    const float* Wq = (const float*)d_in[1];
    const float* Wk = (const float*)d_in[2];
    const float* Wv = (const float*)d_in[3];
    const float* Wp = (const float*)d_in[4];
    const float* bp = (const float*)d_in[5];
    float* out = (float*)d_out;

    static bool attr_done = false;
    if (!attr_done) {
        cudaFuncSetAttribute(gemm2_kernel<0>,
                             cudaFuncAttributeMaxDynamicSharedMemorySize,
                             STAGES * SLOTU * 4);
        cudaFuncSetAttribute(gemm2_kernel<1>,
                             cudaFuncAttributeMaxDynamicSharedMemorySize,
                             STAGES * SLOTU * 4);
        attr_done = true;
    }

    uint32_t* xt  = nullptr;  cudaGetSymbolAddress((void**)&xt,  g_xt);
    uint32_t* wt  = nullptr;  cudaGetSymbolAddress((void**)&wt,  g_wt);
    uint32_t* wpt = nullptr;  cudaGetSymbolAddress((void**)&wpt, g_wpt);
    uint32_t* yb  = nullptr;  cudaGetSymbolAddress((void**)&yb,  g_y);

    // 0) pre-convert operands to tf32 bit patterns
    conv_tf32_kernel<<<16384, 1024>>>((const float4*)x,  (uint4*)xt,  16777216);
    conv_tf32_kernel<<<64, 1024>>>((const float4*)Wq, (uint4*)wt,             65536);
    conv_tf32_kernel<<<64, 1024>>>((const float4*)Wk, (uint4*)(wt + 262144),  65536);
    conv_tf32_kernel<<<64, 1024>>>((const float4*)Wv, (uint4*)(wt + 524288),  65536);
    conv_tf32_kernel<<<64, 1024>>>((const float4*)Wp, (uint4*)wpt,            65536);

    // 1) QKV projection -> g_qkv (tf32 bits)
    gemm2_kernel<0><<<dim3(12, 1024), 512, STAGES * SLOTU * 4>>>(xt, wt, nullptr, nullptr);

    // 2) per-(b,h) causal attention -> g_y (tf32 bits, concat-on-time transpose)
    attn_kernel<<<32768, 64>>>();

    // 3) output projection: out = Y @ Wp^T + bp
    gemm2_kernel<1><<<dim3(4, 1024), 512, STAGES * SLOTU * 4>>>(yb, wpt, bp, out);
}